// round 5
// baseline (speedup 1.0000x reference)
#include <cuda_runtime.h>
#include <cuda_bf16.h>

// Problem constants
#define B_TOT   16384
#define V_STEPS 20
#define F_IN    15
#define H_DIM   256
#define G3      768     // 3*H
#define KPAD    272     // cols: [0..14]=x, [15]=0 pad, [16..271]=h  (K for GRU & layer1)

// ---------------- static device scratch (no allocations allowed) ----------------
__device__ float g_WT[KPAD * G3];        // W_T[k][g]: concat(W_ih | 0 | W_hh), k-major
__device__ float g_bsum[G3];             // b_ih + b_hh
__device__ float g_W1p[1024 * KPAD];     // W1 padded to K=272 with the same col layout
__device__ float g_xin[B_TOT * KPAD];    // [x(15) | 0 | h(256)] per row
__device__ float g_x1[B_TOT * 1024];
__device__ float g_x2[B_TOT * 1024];
__device__ float g_x3[B_TOT * 512];
__device__ float g_x4[B_TOT * 256];

__device__ __forceinline__ float sigmoidf_(float x) {
    return __fdividef(1.f, 1.f + __expf(-x));
}
__device__ __forceinline__ float tanh_(float x) {
    return __fdividef(2.f, 1.f + __expf(-2.f * x)) - 1.f;
}

// ---- packed fp32x2 helpers (SASS FFMA2 path; ptxas never emits this from C++) ----
typedef unsigned long long u64;
union F4U2 { float4 f4; u64 u2[2]; };

__device__ __forceinline__ u64 pack2(float lo, float hi) {
    u64 r; asm("mov.b64 %0, {%1, %2};" : "=l"(r) : "f"(lo), "f"(hi)); return r;
}
__device__ __forceinline__ u64 fma2(u64 a, u64 b, u64 c) {
    u64 d; asm("fma.rn.f32x2 %0, %1, %2, %3;" : "=l"(d) : "l"(a), "l"(b), "l"(c)); return d;
}
__device__ __forceinline__ float2 unpk2(u64 v) {
    float2 f; asm("mov.b64 {%0, %1}, %2;" : "=f"(f.x), "=f"(f.y) : "l"(v)); return f;
}

// ---------------- kernel 0: pack weights ----------------
__global__ void pack_kernel(const float* __restrict__ W_ih, const float* __restrict__ W_hh,
                            const float* __restrict__ b_ih, const float* __restrict__ b_hh,
                            const float* __restrict__ W1) {
    int b = blockIdx.x;
    int k = threadIdx.x;            // 0..271
    if (b < G3) {
        float v;
        if (k < 15)       v = W_ih[b * 15 + k];
        else if (k == 15) v = 0.f;
        else              v = W_hh[b * 256 + (k - 16)];
        g_WT[k * G3 + b] = v;
        if (k == 0) g_bsum[b] = b_ih[b] + b_hh[b];
    } else {
        int n = b - G3;
        float v;
        if (k < 15)       v = W1[n * 271 + k];
        else if (k == 15) v = 0.f;
        else              v = W1[n * 271 + (k - 1)];
        g_W1p[n * KPAD + k] = v;
    }
}

// ---------------- kernel 1: fused GRU over V=20 steps (f32x2 inner loop) ----------------
// grid 128 blocks x 256 threads; block owns 128 batch rows.
__global__ __launch_bounds__(256, 1)
void gru_kernel(const float* __restrict__ state, const float* __restrict__ b_ih) {
    extern __shared__ float smem[];
    float* Xs  = smem;                          // 128*272 = 34816 floats
    float* WtS = smem + 128 * KPAD;             // 8*384   =  3072 floats
    float* hst = WtS + 8 * 384;                 // 64*256  = 16384 floats
    float4* Wt4 = (float4*)WtS;
    const float4* WT4 = (const float4*)g_WT;    // row stride 768/4 = 192 float4

    const int tid = threadIdx.x;
    const int jt  = tid & 31;
    const int rt  = tid >> 5;
    const int bbase = blockIdx.x * 128;

    for (int i = tid; i < 128 * KPAD; i += 256) Xs[i] = 0.f;
    __syncthreads();

    for (int t = 0; t < V_STEPS; t++) {
        for (int i = tid; i < 128 * F_IN; i += 256) {
            int r = i / F_IN, f = i - r * F_IN;
            Xs[r * KPAD + f] = state[(bbase + r) * (V_STEPS * F_IN) + t * F_IN + f];
        }

        for (int rp = 0; rp < 2; rp++) {
            const int rbase = rp * 64;
            for (int jc = 0; jc < 2; jc++) {
                const int jb = jc * 128 + jt * 4;

                u64 accR[8][2], accZ[8][2], accN[8][2], accX[8][2];
                #pragma unroll
                for (int i = 0; i < 8; i++) {
                    accR[i][0]=0ull; accR[i][1]=0ull;
                    accZ[i][0]=0ull; accZ[i][1]=0ull;
                    accN[i][0]=0ull; accN[i][1]=0ull;
                    accX[i][0]=0ull; accX[i][1]=0ull;
                }

                for (int kt = 0; kt < KPAD / 8; kt++) {           // 34 k-tiles of 8
                    __syncthreads();
                    #pragma unroll 3
                    for (int i = tid; i < 768; i += 256) {        // 8 k x 96 float4
                        int k = i / 96, r = i - k * 96;
                        int gate = r >> 5, q = r & 31;
                        Wt4[i] = WT4[(kt * 8 + k) * 192 + gate * 64 + jc * 32 + q];
                    }
                    __syncthreads();

                    if (kt < 2) {
                        // kg in [0,16): also accumulate x-side of n gate.
                        // (kg==15 is the zero-padded column, harmless.)
                        #pragma unroll
                        for (int k = 0; k < 8; k++) {
                            const int kg = kt * 8 + k;
                            u64 xp[8];
                            #pragma unroll
                            for (int i = 0; i < 8; i++) {
                                float xv = Xs[(rbase + rt * 8 + i) * KPAD + kg];
                                xp[i] = pack2(xv, xv);
                            }
                            F4U2 wr, wz, wn;
                            wr.f4 = Wt4[k * 96 + jt];
                            wz.f4 = Wt4[k * 96 + 32 + jt];
                            wn.f4 = Wt4[k * 96 + 64 + jt];
                            #pragma unroll
                            for (int i = 0; i < 8; i++) {
                                accR[i][0] = fma2(xp[i], wr.u2[0], accR[i][0]);
                                accR[i][1] = fma2(xp[i], wr.u2[1], accR[i][1]);
                                accZ[i][0] = fma2(xp[i], wz.u2[0], accZ[i][0]);
                                accZ[i][1] = fma2(xp[i], wz.u2[1], accZ[i][1]);
                                accN[i][0] = fma2(xp[i], wn.u2[0], accN[i][0]);
                                accN[i][1] = fma2(xp[i], wn.u2[1], accN[i][1]);
                                accX[i][0] = fma2(xp[i], wn.u2[0], accX[i][0]);
                                accX[i][1] = fma2(xp[i], wn.u2[1], accX[i][1]);
                            }
                        }
                        if (kt == 1) {
                            // aX complete: spill to its epilogue slot in hst, freeing regs
                            #pragma unroll
                            for (int i = 0; i < 8; i++) {
                                float2 lo = unpk2(accX[i][0]);
                                float2 hi = unpk2(accX[i][1]);
                                *(float4*)&hst[(rt * 8 + i) * 256 + jb] =
                                    make_float4(lo.x, lo.y, hi.x, hi.y);
                            }
                        }
                    } else {
                        #pragma unroll
                        for (int k = 0; k < 8; k++) {
                            const int kg = kt * 8 + k;
                            u64 xp[8];
                            #pragma unroll
                            for (int i = 0; i < 8; i++) {
                                float xv = Xs[(rbase + rt * 8 + i) * KPAD + kg];
                                xp[i] = pack2(xv, xv);
                            }
                            F4U2 wr, wz, wn;
                            wr.f4 = Wt4[k * 96 + jt];
                            wz.f4 = Wt4[k * 96 + 32 + jt];
                            wn.f4 = Wt4[k * 96 + 64 + jt];
                            #pragma unroll
                            for (int i = 0; i < 8; i++) {
                                accR[i][0] = fma2(xp[i], wr.u2[0], accR[i][0]);
                                accR[i][1] = fma2(xp[i], wr.u2[1], accR[i][1]);
                                accZ[i][0] = fma2(xp[i], wz.u2[0], accZ[i][0]);
                                accZ[i][1] = fma2(xp[i], wz.u2[1], accZ[i][1]);
                                accN[i][0] = fma2(xp[i], wn.u2[0], accN[i][0]);
                                accN[i][1] = fma2(xp[i], wn.u2[1], accN[i][1]);
                            }
                        }
                    }
                }

                // gate math
                float4 bR = *(const float4*)(g_bsum + jb);
                float4 bZ = *(const float4*)(g_bsum + 256 + jb);
                float4 bN = *(const float4*)(g_bsum + 512 + jb);
                float4 bX = *(const float4*)(b_ih + 512 + jb);
                float brv[4] = {bR.x, bR.y, bR.z, bR.w};
                float bzv[4] = {bZ.x, bZ.y, bZ.z, bZ.w};
                float bnv[4] = {bN.x, bN.y, bN.z, bN.w};
                float bxv[4] = {bX.x, bX.y, bX.z, bX.w};
                #pragma unroll
                for (int i = 0; i < 8; i++) {
                    int row = rbase + rt * 8 + i;
                    float4 hp4 = *(float4*)&Xs[row * KPAD + 16 + jb];
                    float hpv[4] = {hp4.x, hp4.y, hp4.z, hp4.w};
                    float4 xn4 = *(float4*)&hst[(rt * 8 + i) * 256 + jb];  // spilled aX
                    float xnv[4] = {xn4.x, xn4.y, xn4.z, xn4.w};
                    float2 r01 = unpk2(accR[i][0]), r23 = unpk2(accR[i][1]);
                    float2 z01 = unpk2(accZ[i][0]), z23 = unpk2(accZ[i][1]);
                    float2 n01 = unpk2(accN[i][0]), n23 = unpk2(accN[i][1]);
                    float aRv[4] = {r01.x, r01.y, r23.x, r23.y};
                    float aZv[4] = {z01.x, z01.y, z23.x, z23.y};
                    float aNv[4] = {n01.x, n01.y, n23.x, n23.y};
                    float ov[4];
                    #pragma unroll
                    for (int jj = 0; jj < 4; jj++) {
                        float pr = aRv[jj] + brv[jj];
                        float pz = aZv[jj] + bzv[jj];
                        float xn = xnv[jj] + bxv[jj];
                        float hn = (aNv[jj] + bnv[jj]) - xnv[jj] - xn + xnv[jj];
                        // hn = h-side preact + b_hh_n  == (aN + bsum_n) - (aX + b_ih_n)
                        hn = (aNv[jj] + bnv[jj]) - xn;
                        float rg = sigmoidf_(pr);
                        float zg = sigmoidf_(pz);
                        float ng = tanh_(fmaf(rg, hn, xn));
                        ov[jj] = (1.f - zg) * ng + zg * hpv[jj];
                    }
                    *(float4*)&hst[(rt * 8 + i) * 256 + jb] =
                        make_float4(ov[0], ov[1], ov[2], ov[3]);
                }
            } // jc

            __syncthreads();
            for (int i = tid; i < 64 * 256; i += 256) {
                int rl = i >> 8, c = i & 255;
                Xs[(rbase + rl) * KPAD + 16 + c] = hst[i];
            }
        } // rp
        __syncthreads();
    } // t

    // epilogue: write x_in = [x(t=0) | 0 | h_final]
    for (int i = tid; i < 128 * KPAD; i += 256) {
        int r = i / KPAD, c = i - r * KPAD;
        float v;
        if (c < 15)       v = state[(bbase + r) * (V_STEPS * F_IN) + c];
        else if (c == 15) v = 0.f;
        else              v = Xs[i];
        g_xin[(bbase + r) * KPAD + c] = v;
    }
}

// ---------------- MLP GEMM: C = relu(A @ W^T + b), f32x2 row-paired ----------------
__global__ __launch_bounds__(256)
void gemm_bias_relu(const float* __restrict__ A, const float* __restrict__ W,
                    const float* __restrict__ bias, float* __restrict__ C,
                    int K, int lda, int ldw, int ldc) {
    __shared__ float As[16][132];
    __shared__ float Ws[16][68];
    const int tid = threadIdx.x;
    const int nt = tid & 15, mt = tid >> 4;
    const int nb = blockIdx.x * 64, mb = blockIdx.y * 128;

    u64 acc[4][4];   // [row-pair][j]
    #pragma unroll
    for (int p = 0; p < 4; p++)
        #pragma unroll
        for (int j = 0; j < 4; j++) acc[p][j] = 0ull;

    for (int kt = 0; kt < K; kt += 16) {
        __syncthreads();
        #pragma unroll 2
        for (int i = tid; i < 512; i += 256) {        // A tile 128x16 as float4
            int row = i >> 2, kq = i & 3;
            float4 v = *(const float4*)(A + (mb + row) * lda + kt + kq * 4);
            As[kq * 4 + 0][row] = v.x; As[kq * 4 + 1][row] = v.y;
            As[kq * 4 + 2][row] = v.z; As[kq * 4 + 3][row] = v.w;
        }
        {
            int row = tid >> 2, kq = tid & 3;          // W tile 64x16 as float4
            float4 v = *(const float4*)(W + (nb + row) * ldw + kt + kq * 4);
            Ws[kq * 4 + 0][row] = v.x; Ws[kq * 4 + 1][row] = v.y;
            Ws[kq * 4 + 2][row] = v.z; Ws[kq * 4 + 3][row] = v.w;
        }
        __syncthreads();
        #pragma unroll
        for (int k = 0; k < 16; k++) {
            F4U2 a0, a1;
            a0.f4 = *(float4*)&As[k][mt * 8];
            a1.f4 = *(float4*)&As[k][mt * 8 + 4];
            float4 w = *(float4*)&Ws[k][nt * 4];
            u64 wp[4] = { pack2(w.x, w.x), pack2(w.y, w.y),
                          pack2(w.z, w.z), pack2(w.w, w.w) };
            u64 ap[4] = { a0.u2[0], a0.u2[1], a1.u2[0], a1.u2[1] };
            #pragma unroll
            for (int p = 0; p < 4; p++)
                #pragma unroll
                for (int j = 0; j < 4; j++)
                    acc[p][j] = fma2(ap[p], wp[j], acc[p][j]);
        }
    }

    float4 bb = *(const float4*)(bias + nb + nt * 4);
    float bv[4] = {bb.x, bb.y, bb.z, bb.w};
    #pragma unroll
    for (int p = 0; p < 4; p++) {
        float2 c0 = unpk2(acc[p][0]);
        float2 c1 = unpk2(acc[p][1]);
        float2 c2 = unpk2(acc[p][2]);
        float2 c3 = unpk2(acc[p][3]);
        float4 e; // even row (2p)
        e.x = fmaxf(c0.x + bv[0], 0.f);
        e.y = fmaxf(c1.x + bv[1], 0.f);
        e.z = fmaxf(c2.x + bv[2], 0.f);
        e.w = fmaxf(c3.x + bv[3], 0.f);
        float4 o; // odd row (2p+1)
        o.x = fmaxf(c0.y + bv[0], 0.f);
        o.y = fmaxf(c1.y + bv[1], 0.f);
        o.z = fmaxf(c2.y + bv[2], 0.f);
        o.w = fmaxf(c3.y + bv[3], 0.f);
        *(float4*)(C + (mb + mt * 8 + 2 * p) * ldc + nb + nt * 4) = e;
        *(float4*)(C + (mb + mt * 8 + 2 * p + 1) * ldc + nb + nt * 4) = o;
    }
}

// ---------------- final layer: out = tanh(x4 @ Wp^T + bp), N=1 ----------------
__global__ __launch_bounds__(256)
void final_kernel(const float* __restrict__ x4, const float* __restrict__ Wp,
                  const float* __restrict__ bp, float* __restrict__ out) {
    int warp = (blockIdx.x * 256 + threadIdx.x) >> 5;
    int lane = threadIdx.x & 31;
    if (warp >= B_TOT) return;
    const float* row = x4 + warp * 256;
    float s = 0.f;
    #pragma unroll
    for (int c = lane; c < 256; c += 32) s += row[c] * Wp[c];
    #pragma unroll
    for (int o = 16; o; o >>= 1) s += __shfl_xor_sync(0xffffffffu, s, o);
    if (lane == 0) out[warp] = tanh_(s + bp[0]);
}

// ---------------- host launcher ----------------
extern "C" void kernel_launch(void* const* d_in, const int* in_sizes, int n_in,
                              void* d_out, int out_size) {
    const float* state = (const float*)d_in[0];
    const float* W_ih  = (const float*)d_in[1];
    const float* W_hh  = (const float*)d_in[2];
    const float* b_ih  = (const float*)d_in[3];
    const float* b_hh  = (const float*)d_in[4];
    const float* W1    = (const float*)d_in[5];
    const float* b1    = (const float*)d_in[6];
    const float* W2    = (const float*)d_in[7];
    const float* b2    = (const float*)d_in[8];
    const float* W3    = (const float*)d_in[9];
    const float* b3    = (const float*)d_in[10];
    const float* W4    = (const float*)d_in[11];
    const float* b4    = (const float*)d_in[12];
    const float* Wp    = (const float*)d_in[13];
    const float* bp    = (const float*)d_in[14];
    float* out = (float*)d_out;
    (void)in_sizes; (void)n_in; (void)out_size;

    void *pW1p, *pxin, *px1, *px2, *px3, *px4;
    cudaGetSymbolAddress(&pW1p, g_W1p);
    cudaGetSymbolAddress(&pxin, g_xin);
    cudaGetSymbolAddress(&px1,  g_x1);
    cudaGetSymbolAddress(&px2,  g_x2);
    cudaGetSymbolAddress(&px3,  g_x3);
    cudaGetSymbolAddress(&px4,  g_x4);

    pack_kernel<<<G3 + 1024, KPAD>>>(W_ih, W_hh, b_ih, b_hh, W1);

    constexpr int GRU_SMEM = (128 * KPAD + 8 * 384 + 64 * 256) * 4;   // 217,088 B
    cudaFuncSetAttribute(gru_kernel, cudaFuncAttributeMaxDynamicSharedMemorySize, GRU_SMEM);
    gru_kernel<<<128, 256, GRU_SMEM>>>(state, b_ih);

    gemm_bias_relu<<<dim3(16, 128), 256>>>((const float*)pxin, (const float*)pW1p, b1,
                                           (float*)px1, KPAD, KPAD, KPAD, 1024);
    gemm_bias_relu<<<dim3(16, 128), 256>>>((const float*)px1, W2, b2,
                                           (float*)px2, 1024, 1024, 1024, 1024);
    gemm_bias_relu<<<dim3(8, 128), 256>>>((const float*)px2, W3, b3,
                                          (float*)px3, 1024, 1024, 1024, 512);
    gemm_bias_relu<<<dim3(4, 128), 256>>>((const float*)px3, W4, b4,
                                          (float*)px4, 512, 512, 512, 256);
    final_kernel<<<B_TOT / 8, 256>>>((const float*)px4, Wp, bp, out);
}

// round 8
// speedup vs baseline: 1.6613x; 1.6613x over previous
#include <cuda_runtime.h>
#include <cuda_bf16.h>
#include <stdint.h>

#define B_TOT 16384
#define V_STEPS 20
#define KPAD 272

// MLP scratch
__device__ float g_W1p[1024*KPAD];
__device__ float g_xin[B_TOT*KPAD];
__device__ float g_x1[B_TOT*1024];
__device__ float g_x2[B_TOT*1024];
__device__ float g_x3[B_TOT*512];
__device__ float g_x4[B_TOT*256];
// GRU packed weights bf16 [hl][768][272]: k0-14=W_ih (0 for n-gate), k15=bias, k16+=W_hh
// +64 pad: tail-chunk prefetch reads 16 shorts past the last row (staged, never consumed)
__device__ __align__(16) unsigned short g_Wg[2*768*272 + 64];
// x-side n-gate [hl][256][16]: k0-14=W_ih(n), k15=b_ih(n)
__device__ __align__(16) unsigned short g_Wxn[2*256*16];
__device__ uint32_t g_hstage[128*128*256];   // per-CTA h staging (hi16|lo16)

// smem byte offsets
#define OFF_A_HI 0
#define OFF_A_LO 71680            // 128*280*2
#define OFF_BXN  143360           // [2][256][24 bf16] rows 48B
#define OFF_BS   167936           // [2buf][6][32][40 bf16] rows 80B (64B data = 32 k-elems)
#define GRU_SMEM 198656

__device__ __forceinline__ float sigmoidf_(float x){ return __fdividef(1.f,1.f+__expf(-x)); }
__device__ __forceinline__ float tanh_(float x){ return __fdividef(2.f,1.f+__expf(-2.f*x))-1.f; }
__device__ __forceinline__ uint32_t smem_u32(const void* p){
    uint32_t a; asm("{ .reg .u64 t; cvta.to.shared.u64 t, %1; cvt.u32.u64 %0, t; }":"=r"(a):"l"(p)); return a;
}
__device__ __forceinline__ void ldsm4(uint32_t a, uint32_t* r){
    asm volatile("ldmatrix.sync.aligned.m8n8.x4.shared.b16 {%0,%1,%2,%3}, [%4];"
        : "=r"(r[0]),"=r"(r[1]),"=r"(r[2]),"=r"(r[3]) : "r"(a));
}
__device__ __forceinline__ void ldsm2(uint32_t a, uint32_t* r){
    asm volatile("ldmatrix.sync.aligned.m8n8.x2.shared.b16 {%0,%1}, [%2];"
        : "=r"(r[0]),"=r"(r[1]) : "r"(a));
}
__device__ __forceinline__ void mma16816(float* d, const uint32_t* a, const uint32_t* b){
    asm volatile("mma.sync.aligned.m16n8k16.row.col.f32.bf16.bf16.f32 "
        "{%0,%1,%2,%3}, {%4,%5,%6,%7}, {%8,%9}, {%0,%1,%2,%3};"
        : "+f"(d[0]),"+f"(d[1]),"+f"(d[2]),"+f"(d[3])
        : "r"(a[0]),"r"(a[1]),"r"(a[2]),"r"(a[3]),"r"(b[0]),"r"(b[1]));
}
__device__ __forceinline__ void bfsplit(float v, unsigned short& h, unsigned short& l){
    __nv_bfloat16 hh=__float2bfloat16(v);
    h=__bfloat16_as_ushort(hh);
    l=__bfloat16_as_ushort(__float2bfloat16(v-__bfloat162float(hh)));
}

// ---------------- pack kernels ----------------
__global__ void pack_gru(const float* __restrict__ W_ih, const float* __restrict__ W_hh,
                         const float* __restrict__ b_ih, const float* __restrict__ b_hh){
    int g=blockIdx.x, k=threadIdx.x;       // 768 x 272
    int gate=g>>8;
    float v;
    if(k<15)       v = (gate==2)? 0.f : W_ih[g*15+k];
    else if(k==15) v = (gate==2)? b_hh[g] : (b_ih[g]+b_hh[g]);
    else           v = W_hh[g*256+(k-16)];
    unsigned short h,l; bfsplit(v,h,l);
    g_Wg[g*272+k]=h; g_Wg[208896+g*272+k]=l;
    if(g>=512 && k<16){
        float w = (k<15)? W_ih[g*15+k] : b_ih[g];
        unsigned short h2,l2; bfsplit(w,h2,l2);
        g_Wxn[(g-512)*16+k]=h2; g_Wxn[4096+(g-512)*16+k]=l2;
    }
}
__global__ void pack_w1(const float* __restrict__ W1){
    int n=blockIdx.x, k=threadIdx.x;
    g_W1p[n*KPAD+k] = (k<15)? W1[n*271+k] : (k==15? 0.f : W1[n*271+k-1]);
}

// ---------------- GRU: mma.sync bf16-split, persistent 20 steps ----------------
__global__ __launch_bounds__(256,1) void gru_mma_kernel(const float* __restrict__ state){
    extern __shared__ __align__(16) unsigned char sm[];
    const uint32_t sb=smem_u32(sm);
    const int tid=threadIdx.x, wid=tid>>5, l=tid&31, ll=l&15;
    const int wm=wid&1, wn=wid>>1;
    const int cta=blockIdx.x, bbase=cta*128;

    for(int i=tid;i<143360/16;i+=256) ((uint4*)sm)[i]=make_uint4(0,0,0,0);
    for(int i=tid;i<1024;i+=256){
        int u=i&1, n=(i>>1)&255, hl=i>>9;
        uint4 v=*(const uint4*)(g_Wxn + hl*4096 + n*16 + u*8);
        *(uint4*)(sm+OFF_BXN + hl*12288 + n*48 + u*16)=v;
    }
    __syncthreads();

    const uint32_t aoff  = (uint32_t)(ll*560 + (l>>4)*16);
    const uint32_t boffn = (uint32_t)((l&7)*80 + (ll>>3)*16) + wn*8*80;
    const uint32_t bxoff = (uint32_t)((l&7)*48 + (ll>>3)*16) + wn*8*48;

    for(int t=0;t<V_STEPS;t++){
        {   // x cols 0..15 (k15 = 1.0 bias column)
            int row=tid>>1, k0=(tid&1)*8;
            union{uint4 q; unsigned short s[8];} hi,lo;
            #pragma unroll
            for(int j=0;j<8;j++){
                int k=k0+j;
                float v=(k<15)? state[(size_t)(bbase+row)*300+t*15+k] : (k==15?1.f:0.f);
                bfsplit(v,hi.s[j],lo.s[j]);
            }
            *(uint4*)(sm+OFF_A_HI+row*560+k0*2)=hi.q;
            *(uint4*)(sm+OFF_A_LO+row*560+k0*2)=lo.q;
        }
        __syncthreads();

        for(int hb=0;hb<8;hb++){
            float aR[4][4],aZ[4][4],aH[4][4],aX[4][4];
            #pragma unroll
            for(int m2=0;m2<4;m2++)
                #pragma unroll
                for(int e=0;e<4;e++){ aR[m2][e]=0.f;aZ[m2][e]=0.f;aH[m2][e]=0.f;aX[m2][e]=0.f; }

            uint32_t bxh[2],bxl[2];
            { uint32_t a0=sb+OFF_BXN + hb*32*48 + bxoff;
              ldsm2(a0,bxh); ldsm2(a0+12288,bxl); }

            // stage chunk 0 (k elements 0..31)
            uint4 ldv[3];
            #pragma unroll
            for(int j=0;j<3;j++){
                int i=tid+j*256, u=i&3, n=(i>>2)&31, gh=i>>7;
                ldv[j]=*(const uint4*)(g_Wg + (gh&1)*208896 + ((gh>>1)*256+hb*32+n)*272 + u*8);
            }
            #pragma unroll
            for(int j=0;j<3;j++){
                int i=tid+j*256, u=i&3, n=(i>>2)&31, gh=i>>7;
                *(uint4*)(sm+OFF_BS + (gh*32+n)*80 + u*16)=ldv[j];
            }
            __syncthreads();

            // 9 chunks of 32 k-elems (last chunk: 16) => 17 k16 MMA steps
            for(int kc=0;kc<9;kc++){
                int buf=kc&1;
                if(kc<8){
                    #pragma unroll
                    for(int j=0;j<3;j++){
                        int i=tid+j*256, u=i&3, n=(i>>2)&31, gh=i>>7;
                        ldv[j]=*(const uint4*)(g_Wg + (gh&1)*208896 +
                               ((gh>>1)*256+hb*32+n)*272 + (kc+1)*32 + u*8);
                    }
                }
                const int ns=(kc==8)?1:2;
                for(int s=0;s<ns;s++){
                    uint32_t bh[3][2], bl[3][2];
                    #pragma unroll
                    for(int g=0;g<3;g++){
                        uint32_t base=sb+OFF_BS + buf*15360 + g*2*2560 + boffn + s*32;
                        ldsm2(base, bh[g]); ldsm2(base+2560, bl[g]);
                    }
                    #pragma unroll
                    for(int mt=0;mt<4;mt++){
                        uint32_t ah[4],al[4];
                        uint32_t abase=sb + (wm*64+mt*16)*560 + kc*64 + s*32 + aoff;
                        ldsm4(abase+OFF_A_HI, ah);
                        ldsm4(abase+OFF_A_LO, al);
                        mma16816(aR[mt],ah,bh[0]); mma16816(aR[mt],al,bh[0]); mma16816(aR[mt],ah,bl[0]);
                        mma16816(aZ[mt],ah,bh[1]); mma16816(aZ[mt],al,bh[1]); mma16816(aZ[mt],ah,bl[1]);
                        mma16816(aH[mt],ah,bh[2]); mma16816(aH[mt],al,bh[2]); mma16816(aH[mt],ah,bl[2]);
                        if(kc==0 && s==0){
                            mma16816(aX[mt],ah,bxh); mma16816(aX[mt],al,bxh); mma16816(aX[mt],ah,bxl);
                        }
                    }
                }
                if(kc<8){
                    #pragma unroll
                    for(int j=0;j<3;j++){
                        int i=tid+j*256, u=i&3, n=(i>>2)&31, gh=i>>7;
                        *(uint4*)(sm+OFF_BS + (buf^1)*15360 + (gh*32+n)*80 + u*16)=ldv[j];
                    }
                    __syncthreads();
                }
            }
            // epilogue: gate math, stage h_new in gmem
            #pragma unroll
            for(int mt=0;mt<4;mt++){
                #pragma unroll
                for(int e=0;e<4;e++){
                    int row=wm*64+mt*16+(l>>2)+(e>>1)*8;
                    int hcol=hb*32+wn*8+2*(l&3)+(e&1);
                    float hp=__bfloat162float(*(__nv_bfloat16*)(sm+OFF_A_HI+row*560+(16+hcol)*2))
                            +__bfloat162float(*(__nv_bfloat16*)(sm+OFF_A_LO+row*560+(16+hcol)*2));
                    float r=sigmoidf_(aR[mt][e]), z=sigmoidf_(aZ[mt][e]);
                    float n=tanh_(fmaf(r,aH[mt][e],aX[mt][e]));
                    float hv=(1.f-z)*n+z*hp;
                    unsigned short hs,ls; bfsplit(hv,hs,ls);
                    g_hstage[(size_t)cta*32768 + row*256 + hcol]=((uint32_t)hs<<16)|ls;
                }
            }
            __syncthreads();   // protect Bs buf reuse + order staged writes
        } // hb

        // commit staged h into A (h_t)
        {
            int row=tid>>1, cb=(tid&1)*128;
            const uint4* src=(const uint4*)(g_hstage + (size_t)cta*32768 + row*256 + cb);
            #pragma unroll
            for(int g8=0;g8<16;g8++){
                uint4 w0=src[g8*2], w1=src[g8*2+1];
                uint32_t ws[8]={w0.x,w0.y,w0.z,w0.w,w1.x,w1.y,w1.z,w1.w};
                union{uint4 q;unsigned short s[8];} hi,lo;
                #pragma unroll
                for(int j=0;j<8;j++){ hi.s[j]=(unsigned short)(ws[j]>>16); lo.s[j]=(unsigned short)(ws[j]&0xFFFFu); }
                *(uint4*)(sm+OFF_A_HI+row*560+(16+cb+g8*8)*2)=hi.q;
                *(uint4*)(sm+OFF_A_LO+row*560+(16+cb+g8*8)*2)=lo.q;
            }
        }
        __syncthreads();
    } // t

    // write x_in = [x(t=0,15) | 0 | h]
    for(int i=tid;i<128*KPAD;i+=256){
        int r=i/KPAD, c=i-r*KPAD;
        float v;
        if(c<15) v=state[(size_t)(bbase+r)*300+c];
        else if(c==15) v=0.f;
        else v=__bfloat162float(*(__nv_bfloat16*)(sm+OFF_A_HI+r*560+c*2))
              +__bfloat162float(*(__nv_bfloat16*)(sm+OFF_A_LO+r*560+c*2));
        g_xin[(size_t)(bbase+r)*KPAD+c]=v;
    }
}

// ---------------- MLP GEMM (f32x2, unchanged) ----------------
typedef unsigned long long u64;
union F4U2 { float4 f4; u64 u2[2]; };
__device__ __forceinline__ u64 pack2(float a,float b){ u64 r; asm("mov.b64 %0, {%1, %2};":"=l"(r):"f"(a),"f"(b)); return r; }
__device__ __forceinline__ u64 fma2(u64 a,u64 b,u64 c){ u64 d; asm("fma.rn.f32x2 %0, %1, %2, %3;":"=l"(d):"l"(a),"l"(b),"l"(c)); return d; }
__device__ __forceinline__ float2 unpk2(u64 v){ float2 f; asm("mov.b64 {%0, %1}, %2;":"=f"(f.x),"=f"(f.y):"l"(v)); return f; }

__global__ __launch_bounds__(256)
void gemm_bias_relu(const float* __restrict__ A, const float* __restrict__ W,
                    const float* __restrict__ bias, float* __restrict__ C,
                    int K, int lda, int ldw, int ldc){
    __shared__ float As[16][132];
    __shared__ float Ws[16][68];
    const int tid=threadIdx.x, nt=tid&15, mt=tid>>4;
    const int nb=blockIdx.x*64, mb=blockIdx.y*128;
    u64 acc[4][4];
    #pragma unroll
    for(int p=0;p<4;p++){ acc[p][0]=0ull;acc[p][1]=0ull;acc[p][2]=0ull;acc[p][3]=0ull; }
    for(int kt=0;kt<K;kt+=16){
        __syncthreads();
        #pragma unroll 2
        for(int i=tid;i<512;i+=256){
            int row=i>>2,kq=i&3;
            float4 v=*(const float4*)(A+(size_t)(mb+row)*lda+kt+kq*4);
            As[kq*4+0][row]=v.x;As[kq*4+1][row]=v.y;As[kq*4+2][row]=v.z;As[kq*4+3][row]=v.w;
        }
        { int row=tid>>2,kq=tid&3;
          float4 v=*(const float4*)(W+(size_t)(nb+row)*ldw+kt+kq*4);
          Ws[kq*4+0][row]=v.x;Ws[kq*4+1][row]=v.y;Ws[kq*4+2][row]=v.z;Ws[kq*4+3][row]=v.w; }
        __syncthreads();
        #pragma unroll
        for(int k=0;k<16;k++){
            F4U2 a0,a1; a0.f4=*(float4*)&As[k][mt*8]; a1.f4=*(float4*)&As[k][mt*8+4];
            float4 w=*(float4*)&Ws[k][nt*4];
            u64 wp[4]={pack2(w.x,w.x),pack2(w.y,w.y),pack2(w.z,w.z),pack2(w.w,w.w)};
            u64 ap[4]={a0.u2[0],a0.u2[1],a1.u2[0],a1.u2[1]};
            #pragma unroll
            for(int p=0;p<4;p++)
                #pragma unroll
                for(int j=0;j<4;j++) acc[p][j]=fma2(ap[p],wp[j],acc[p][j]);
        }
    }
    float4 bb=*(const float4*)(bias+nb+nt*4);
    float bv[4]={bb.x,bb.y,bb.z,bb.w};
    #pragma unroll
    for(int p=0;p<4;p++){
        float2 c0=unpk2(acc[p][0]),c1=unpk2(acc[p][1]),c2=unpk2(acc[p][2]),c3=unpk2(acc[p][3]);
        float4 e,o;
        e.x=fmaxf(c0.x+bv[0],0.f);e.y=fmaxf(c1.x+bv[1],0.f);e.z=fmaxf(c2.x+bv[2],0.f);e.w=fmaxf(c3.x+bv[3],0.f);
        o.x=fmaxf(c0.y+bv[0],0.f);o.y=fmaxf(c1.y+bv[1],0.f);o.z=fmaxf(c2.y+bv[2],0.f);o.w=fmaxf(c3.y+bv[3],0.f);
        *(float4*)(C+(size_t)(mb+mt*8+2*p)*ldc+nb+nt*4)=e;
        *(float4*)(C+(size_t)(mb+mt*8+2*p+1)*ldc+nb+nt*4)=o;
    }
}

__global__ __launch_bounds__(256)
void final_kernel(const float* __restrict__ x4, const float* __restrict__ Wp,
                  const float* __restrict__ bp, float* __restrict__ out){
    int warp=(blockIdx.x*256+threadIdx.x)>>5, lane=threadIdx.x&31;
    if(warp>=B_TOT) return;
    const float* row=x4+(size_t)warp*256;
    float s=0.f;
    #pragma unroll
    for(int c=lane;c<256;c+=32) s+=row[c]*Wp[c];
    #pragma unroll
    for(int o=16;o;o>>=1) s+=__shfl_xor_sync(0xffffffffu,s,o);
    if(lane==0) out[warp]=tanh_(s+bp[0]);
}

// ---------------- host launcher ----------------
extern "C" void kernel_launch(void* const* d_in, const int* in_sizes, int n_in,
                              void* d_out, int out_size){
    const float* state=(const float*)d_in[0];
    const float* W_ih=(const float*)d_in[1];
    const float* W_hh=(const float*)d_in[2];
    const float* b_ih=(const float*)d_in[3];
    const float* b_hh=(const float*)d_in[4];
    const float* W1=(const float*)d_in[5];
    const float* b1=(const float*)d_in[6];
    const float* W2=(const float*)d_in[7];
    const float* b2=(const float*)d_in[8];
    const float* W3=(const float*)d_in[9];
    const float* b3=(const float*)d_in[10];
    const float* W4=(const float*)d_in[11];
    const float* b4=(const float*)d_in[12];
    const float* Wp=(const float*)d_in[13];
    const float* bp=(const float*)d_in[14];
    float* out=(float*)d_out;
    (void)in_sizes;(void)n_in;(void)out_size;

    void *pW1p,*pxin,*px1,*px2,*px3,*px4;
    cudaGetSymbolAddress(&pW1p,g_W1p);
    cudaGetSymbolAddress(&pxin,g_xin);
    cudaGetSymbolAddress(&px1,g_x1);
    cudaGetSymbolAddress(&px2,g_x2);
    cudaGetSymbolAddress(&px3,g_x3);
    cudaGetSymbolAddress(&px4,g_x4);

    pack_gru<<<768,272>>>(W_ih,W_hh,b_ih,b_hh);
    pack_w1<<<1024,KPAD>>>(W1);

    cudaFuncSetAttribute(gru_mma_kernel, cudaFuncAttributeMaxDynamicSharedMemorySize, GRU_SMEM);
    gru_mma_kernel<<<128,256,GRU_SMEM>>>(state);

    gemm_bias_relu<<<dim3(16,128),256>>>((const float*)pxin,(const float*)pW1p,b1,(float*)px1,KPAD,KPAD,KPAD,1024);
    gemm_bias_relu<<<dim3(16,128),256>>>((const float*)px1,W2,b2,(float*)px2,1024,1024,1024,1024);
    gemm_bias_relu<<<dim3(8,128),256>>>((const float*)px2,W3,b3,(float*)px3,1024,1024,1024,512);
    gemm_bias_relu<<<dim3(4,128),256>>>((const float*)px3,W4,b4,(float*)px4,512,512,512,256);
    final_kernel<<<B_TOT/8,256>>>((const float*)px4,Wp,bp,out);
}

// round 10
// speedup vs baseline: 2.1032x; 1.2660x over previous
#include <cuda_runtime.h>
#include <cuda_bf16.h>
#include <stdint.h>

#define B_TOT 16384
#define V_STEPS 20

// ---- activation buffers: packed bf16 pair (hi<<16 | lo) per element ----
__device__ uint32_t g_xin[B_TOT*288];
__device__ uint32_t g_x1[B_TOT*1024];
__device__ uint32_t g_x2[B_TOT*1024];
__device__ uint32_t g_x3[B_TOT*512];
__device__ uint32_t g_x4[B_TOT*256];
// MLP weights bf16 planes [hl][N][Kp] per layer, concatenated
#define WO1 0
#define WO2 589824
#define WO3 (WO2+2097152)
#define WO4 (WO3+1048576)
__device__ __align__(16) unsigned short g_Wm[WO4+262144];
// GRU packed weights bf16 [hl][768][272] (+pad for tail prefetch)
__device__ __align__(16) unsigned short g_Wg[2*768*272 + 64];
__device__ __align__(16) unsigned short g_Wxn[2*256*16];
__device__ uint32_t g_hstage[128*128*256];

// GRU smem offsets
#define OFF_A_HI 0
#define OFF_A_LO 71680
#define OFF_BXN  143360
#define OFF_BS   167936
#define GRU_SMEM 198656
#define MLP_SMEM 61440

__device__ __forceinline__ float sigmoidf_(float x){ return __fdividef(1.f,1.f+__expf(-x)); }
__device__ __forceinline__ float tanh_(float x){ return __fdividef(2.f,1.f+__expf(-2.f*x))-1.f; }
__device__ __forceinline__ uint32_t smem_u32(const void* p){
    uint32_t a; asm("{ .reg .u64 t; cvta.to.shared.u64 t, %1; cvt.u32.u64 %0, t; }":"=r"(a):"l"(p)); return a;
}
__device__ __forceinline__ void ldsm4(uint32_t a, uint32_t* r){
    asm volatile("ldmatrix.sync.aligned.m8n8.x4.shared.b16 {%0,%1,%2,%3}, [%4];"
        : "=r"(r[0]),"=r"(r[1]),"=r"(r[2]),"=r"(r[3]) : "r"(a));
}
__device__ __forceinline__ void ldsm2(uint32_t a, uint32_t* r){
    asm volatile("ldmatrix.sync.aligned.m8n8.x2.shared.b16 {%0,%1}, [%2];"
        : "=r"(r[0]),"=r"(r[1]) : "r"(a));
}
__device__ __forceinline__ void mma16816(float* d, const uint32_t* a, const uint32_t* b){
    asm volatile("mma.sync.aligned.m16n8k16.row.col.f32.bf16.bf16.f32 "
        "{%0,%1,%2,%3}, {%4,%5,%6,%7}, {%8,%9}, {%0,%1,%2,%3};"
        : "+f"(d[0]),"+f"(d[1]),"+f"(d[2]),"+f"(d[3])
        : "r"(a[0]),"r"(a[1]),"r"(a[2]),"r"(a[3]),"r"(b[0]),"r"(b[1]));
}
__device__ __forceinline__ void bfsplit(float v, unsigned short& h, unsigned short& l){
    __nv_bfloat16 hh=__float2bfloat16(v);
    h=__bfloat16_as_ushort(hh);
    l=__bfloat16_as_ushort(__float2bfloat16(v-__bfloat162float(hh)));
}
__device__ __forceinline__ uint32_t bfpack(float v){
    unsigned short h,l; bfsplit(v,h,l); return ((uint32_t)h<<16)|l;
}
__device__ __forceinline__ float bfunpk(uint32_t p){
    unsigned short h=(unsigned short)(p>>16), l=(unsigned short)(p&0xffffu);
    return __bfloat162float(*(__nv_bfloat16*)&h)+__bfloat162float(*(__nv_bfloat16*)&l);
}

// ---------------- pack kernels ----------------
__global__ void pack_gru(const float* __restrict__ W_ih, const float* __restrict__ W_hh,
                         const float* __restrict__ b_ih, const float* __restrict__ b_hh){
    int g=blockIdx.x, k=threadIdx.x;
    int gate=g>>8;
    float v;
    if(k<15)       v = (gate==2)? 0.f : W_ih[g*15+k];
    else if(k==15) v = (gate==2)? b_hh[g] : (b_ih[g]+b_hh[g]);
    else           v = W_hh[g*256+(k-16)];
    unsigned short h,l; bfsplit(v,h,l);
    g_Wg[g*272+k]=h; g_Wg[208896+g*272+k]=l;
    if(g>=512 && k<16){
        float w = (k<15)? W_ih[g*15+k] : b_ih[g];
        unsigned short h2,l2; bfsplit(w,h2,l2);
        g_Wxn[(g-512)*16+k]=h2; g_Wxn[4096+(g-512)*16+k]=l2;
    }
}
// pack an MLP weight matrix into bf16 hi/lo planes [hl][N][Kp]
__global__ void pack_mlp(const float* __restrict__ W, unsigned short* __restrict__ dst,
                         int N, int K, int Kp, int l1mode){
    int n=blockIdx.x;
    for(int k=threadIdx.x;k<Kp;k+=256){
        float v=0.f;
        if(l1mode){ if(k<15) v=W[n*271+k]; else if(k>=16&&k<272) v=W[n*271+k-1]; }
        else if(k<K) v=W[(size_t)n*K+k];
        unsigned short h,l; bfsplit(v,h,l);
        dst[(size_t)n*Kp+k]=h;
        dst[(size_t)N*Kp+(size_t)n*Kp+k]=l;
    }
}

// ---------------- GRU: mma.sync bf16-split, persistent 20 steps ----------------
__global__ __launch_bounds__(256,1) void gru_mma_kernel(const float* __restrict__ state){
    extern __shared__ __align__(16) unsigned char sm[];
    const uint32_t sb=smem_u32(sm);
    const int tid=threadIdx.x, wid=tid>>5, l=tid&31, ll=l&15;
    const int wm=wid&1, wn=wid>>1;
    const int cta=blockIdx.x, bbase=cta*128;

    for(int i=tid;i<143360/16;i+=256) ((uint4*)sm)[i]=make_uint4(0,0,0,0);
    for(int i=tid;i<1024;i+=256){
        int u=i&1, n=(i>>1)&255, hl=i>>9;
        uint4 v=*(const uint4*)(g_Wxn + hl*4096 + n*16 + u*8);
        *(uint4*)(sm+OFF_BXN + hl*12288 + n*48 + u*16)=v;
    }
    __syncthreads();

    const uint32_t aoff  = (uint32_t)(ll*560 + (l>>4)*16);
    const uint32_t boffn = (uint32_t)((l&7)*80 + (ll>>3)*16) + wn*8*80;
    const uint32_t bxoff = (uint32_t)((l&7)*48 + (ll>>3)*16) + wn*8*48;

    for(int t=0;t<V_STEPS;t++){
        {
            int row=tid>>1, k0=(tid&1)*8;
            union{uint4 q; unsigned short s[8];} hi,lo;
            #pragma unroll
            for(int j=0;j<8;j++){
                int k=k0+j;
                float v=(k<15)? state[(size_t)(bbase+row)*300+t*15+k] : (k==15?1.f:0.f);
                bfsplit(v,hi.s[j],lo.s[j]);
            }
            *(uint4*)(sm+OFF_A_HI+row*560+k0*2)=hi.q;
            *(uint4*)(sm+OFF_A_LO+row*560+k0*2)=lo.q;
        }
        __syncthreads();

        for(int hb=0;hb<8;hb++){
            float aR[4][4],aZ[4][4],aH[4][4],aX[4][4];
            #pragma unroll
            for(int m2=0;m2<4;m2++)
                #pragma unroll
                for(int e=0;e<4;e++){ aR[m2][e]=0.f;aZ[m2][e]=0.f;aH[m2][e]=0.f;aX[m2][e]=0.f; }

            uint32_t bxh[2],bxl[2];
            { uint32_t a0=sb+OFF_BXN + hb*32*48 + bxoff;
              ldsm2(a0,bxh); ldsm2(a0+12288,bxl); }

            uint4 ldv[3];
            #pragma unroll
            for(int j=0;j<3;j++){
                int i=tid+j*256, u=i&3, n=(i>>2)&31, gh=i>>7;
                ldv[j]=*(const uint4*)(g_Wg + (gh&1)*208896 + ((gh>>1)*256+hb*32+n)*272 + u*8);
            }
            #pragma unroll
            for(int j=0;j<3;j++){
                int i=tid+j*256, u=i&3, n=(i>>2)&31, gh=i>>7;
                *(uint4*)(sm+OFF_BS + (gh*32+n)*80 + u*16)=ldv[j];
            }
            __syncthreads();

            for(int kc=0;kc<9;kc++){
                int buf=kc&1;
                if(kc<8){
                    #pragma unroll
                    for(int j=0;j<3;j++){
                        int i=tid+j*256, u=i&3, n=(i>>2)&31, gh=i>>7;
                        ldv[j]=*(const uint4*)(g_Wg + (gh&1)*208896 +
                               ((gh>>1)*256+hb*32+n)*272 + (kc+1)*32 + u*8);
                    }
                }
                const int ns=(kc==8)?1:2;
                for(int s=0;s<ns;s++){
                    uint32_t bh[3][2], bl[3][2];
                    #pragma unroll
                    for(int g=0;g<3;g++){
                        uint32_t base=sb+OFF_BS + buf*15360 + g*2*2560 + boffn + s*32;
                        ldsm2(base, bh[g]); ldsm2(base+2560, bl[g]);
                    }
                    #pragma unroll
                    for(int mt=0;mt<4;mt++){
                        uint32_t ah[4],al[4];
                        uint32_t abase=sb + (wm*64+mt*16)*560 + kc*64 + s*32 + aoff;
                        ldsm4(abase+OFF_A_HI, ah);
                        ldsm4(abase+OFF_A_LO, al);
                        mma16816(aR[mt],ah,bh[0]); mma16816(aR[mt],al,bh[0]); mma16816(aR[mt],ah,bl[0]);
                        mma16816(aZ[mt],ah,bh[1]); mma16816(aZ[mt],al,bh[1]); mma16816(aZ[mt],ah,bl[1]);
                        mma16816(aH[mt],ah,bh[2]); mma16816(aH[mt],al,bh[2]); mma16816(aH[mt],ah,bl[2]);
                        if(kc==0 && s==0){
                            mma16816(aX[mt],ah,bxh); mma16816(aX[mt],al,bxh); mma16816(aX[mt],ah,bxl);
                        }
                    }
                }
                if(kc<8){
                    #pragma unroll
                    for(int j=0;j<3;j++){
                        int i=tid+j*256, u=i&3, n=(i>>2)&31, gh=i>>7;
                        *(uint4*)(sm+OFF_BS + (buf^1)*15360 + (gh*32+n)*80 + u*16)=ldv[j];
                    }
                    __syncthreads();
                }
            }
            #pragma unroll
            for(int mt=0;mt<4;mt++){
                #pragma unroll
                for(int e=0;e<4;e++){
                    int row=wm*64+mt*16+(l>>2)+(e>>1)*8;
                    int hcol=hb*32+wn*8+2*(l&3)+(e&1);
                    float hp=__bfloat162float(*(__nv_bfloat16*)(sm+OFF_A_HI+row*560+(16+hcol)*2))
                            +__bfloat162float(*(__nv_bfloat16*)(sm+OFF_A_LO+row*560+(16+hcol)*2));
                    float r=sigmoidf_(aR[mt][e]), z=sigmoidf_(aZ[mt][e]);
                    float n=tanh_(fmaf(r,aH[mt][e],aX[mt][e]));
                    float hv=(1.f-z)*n+z*hp;
                    unsigned short hs,ls; bfsplit(hv,hs,ls);
                    g_hstage[(size_t)cta*32768 + row*256 + hcol]=((uint32_t)hs<<16)|ls;
                }
            }
            __syncthreads();
        } // hb

        {
            int row=tid>>1, cb=(tid&1)*128;
            const uint4* src=(const uint4*)(g_hstage + (size_t)cta*32768 + row*256 + cb);
            #pragma unroll
            for(int g8=0;g8<16;g8++){
                uint4 w0=src[g8*2], w1=src[g8*2+1];
                uint32_t ws[8]={w0.x,w0.y,w0.z,w0.w,w1.x,w1.y,w1.z,w1.w};
                union{uint4 q;unsigned short s[8];} hi,lo;
                #pragma unroll
                for(int j=0;j<8;j++){ hi.s[j]=(unsigned short)(ws[j]>>16); lo.s[j]=(unsigned short)(ws[j]&0xFFFFu); }
                *(uint4*)(sm+OFF_A_HI+row*560+(16+cb+g8*8)*2)=hi.q;
                *(uint4*)(sm+OFF_A_LO+row*560+(16+cb+g8*8)*2)=lo.q;
            }
        }
        __syncthreads();
    } // t

    // write packed x_in = [x(t=0,15) | 0 | h(256) | 0-pad to 288]
    for(int i=tid;i<128*288;i+=256){
        int r=i/288, c=i-r*288;
        uint32_t pk;
        if(c<15) pk=bfpack(state[(size_t)(bbase+r)*300+c]);
        else if(c==15 || c>=272) pk=0u;
        else pk=((uint32_t)(*(unsigned short*)(sm+OFF_A_HI+r*560+c*2))<<16)
               | (uint32_t)(*(unsigned short*)(sm+OFF_A_LO+r*560+c*2));
        g_xin[(size_t)(bbase+r)*288+c]=pk;
    }
}

// ---------------- MLP GEMM: mma.sync bf16-split, packed activations ----------------
// C[M,N] = relu(A@W^T + b); A packed u32 [M][Kp]; W planes [hl][N][Kp]; C packed u32.
// block: 128M x 64N, 8 warps (2m x 4n); k-chunks of 32, double buffered.
// smem: A[buf][hl][128][80B] = 40960; B at 40960 + buf*10240 + hl*5120 + row*80.
__global__ __launch_bounds__(256) void gemm_mma(const uint32_t* __restrict__ A,
        const unsigned short* __restrict__ W, const float* __restrict__ bias,
        uint32_t* __restrict__ C, int Kp, int N){
    extern __shared__ __align__(16) unsigned char sm[];
    const uint32_t sb=smem_u32(sm);
    const int tid=threadIdx.x, wid=tid>>5, l=tid&31;
    const int wm=wid&1, wn=wid>>1;
    const int nb=blockIdx.x*64, mb=blockIdx.y*128;
    const int nch=Kp>>5;
    const size_t wplane=(size_t)N*Kp;

    float acc[4][2][4];
    #pragma unroll
    for(int mt=0;mt<4;mt++)
        #pragma unroll
        for(int ng=0;ng<2;ng++)
            #pragma unroll
            for(int e=0;e<4;e++) acc[mt][ng][e]=0.f;

    const int arow=tid>>3, au=tid&7;        // A: 4 rows/thread (stride 32), 8B per plane
    const int brow=tid>>2, bu=tid&3;        // B: 1 row/thread, 16B per plane
    uint4 av[4], bv[2];

    #define LOAD_AB(kc) { \
        _Pragma("unroll") \
        for(int j=0;j<4;j++) \
            av[j]=*(const uint4*)(A + (size_t)(mb+arow+j*32)*Kp + (kc)*32 + au*4); \
        bv[0]=*(const uint4*)(W + (size_t)(nb+brow)*Kp + (kc)*32 + bu*8); \
        bv[1]=*(const uint4*)(W + wplane + (size_t)(nb+brow)*Kp + (kc)*32 + bu*8); }
    #define STORE_AB(buf) { \
        _Pragma("unroll") \
        for(int j=0;j<4;j++){ \
            uint4 v=av[j]; int ro=(arow+j*32)*80+au*8; \
            *(uint2*)(sm + (buf)*20480 + ro) = \
                make_uint2((v.x>>16)|(v.y&0xffff0000u),(v.z>>16)|(v.w&0xffff0000u)); \
            *(uint2*)(sm + 10240 + (buf)*20480 + ro) = \
                make_uint2((v.x&0xffffu)|(v.y<<16),(v.z&0xffffu)|(v.w<<16)); } \
        *(uint4*)(sm + 40960 + (buf)*10240 + brow*80 + bu*16)=bv[0]; \
        *(uint4*)(sm + 40960 + (buf)*10240 + 5120 + brow*80 + bu*16)=bv[1]; }

    LOAD_AB(0); STORE_AB(0);
    __syncthreads();

    const uint32_t aoff=(uint32_t)((l&15)*80 + (l>>4)*16);
    const uint32_t boff=(uint32_t)((wn*16+(l&7))*80 + ((l>>3)&1)*16);

    for(int kc=0;kc<nch;kc++){
        int buf=kc&1;
        if(kc+1<nch) LOAD_AB(kc+1);
        #pragma unroll
        for(int s=0;s<2;s++){
            uint32_t bh[2][2], bl[2][2];
            #pragma unroll
            for(int ng=0;ng<2;ng++){
                uint32_t base=sb + 40960 + buf*10240 + boff + ng*8*80 + s*32;
                ldsm2(base, bh[ng]); ldsm2(base+5120, bl[ng]);
            }
            #pragma unroll
            for(int mt=0;mt<4;mt++){
                uint32_t ah[4],al[4];
                uint32_t abase=sb + buf*20480 + (wm*64+mt*16)*80 + s*32 + aoff;
                ldsm4(abase, ah); ldsm4(abase+10240, al);
                #pragma unroll
                for(int ng=0;ng<2;ng++){
                    mma16816(acc[mt][ng],ah,bh[ng]);
                    mma16816(acc[mt][ng],al,bh[ng]);
                    mma16816(acc[mt][ng],ah,bl[ng]);
                }
            }
        }
        if(kc+1<nch){ STORE_AB(buf^1); __syncthreads(); }
    }

    #pragma unroll
    for(int mt=0;mt<4;mt++)
        #pragma unroll
        for(int ng=0;ng<2;ng++)
            #pragma unroll
            for(int e=0;e<4;e++){
                int row=mb + wm*64+mt*16+(l>>2)+(e>>1)*8;
                int col=nb + wn*16+ng*8+2*(l&3)+(e&1);
                float v=fmaxf(acc[mt][ng][e]+__ldg(bias+col),0.f);
                C[(size_t)row*N+col]=bfpack(v);
            }
    #undef LOAD_AB
    #undef STORE_AB
}

// ---------------- final layer: out = tanh(x4 @ Wp^T + bp) ----------------
__global__ __launch_bounds__(256)
void final_kernel(const uint32_t* __restrict__ x4, const float* __restrict__ Wp,
                  const float* __restrict__ bp, float* __restrict__ out){
    int warp=(blockIdx.x*256+threadIdx.x)>>5, lane=threadIdx.x&31;
    if(warp>=B_TOT) return;
    const uint32_t* row=x4+(size_t)warp*256;
    float s=0.f;
    #pragma unroll
    for(int c=lane;c<256;c+=32) s+=bfunpk(row[c])*Wp[c];
    #pragma unroll
    for(int o=16;o;o>>=1) s+=__shfl_xor_sync(0xffffffffu,s,o);
    if(lane==0) out[warp]=tanh_(s+bp[0]);
}

// ---------------- host launcher ----------------
extern "C" void kernel_launch(void* const* d_in, const int* in_sizes, int n_in,
                              void* d_out, int out_size){
    const float* state=(const float*)d_in[0];
    const float* W_ih=(const float*)d_in[1];
    const float* W_hh=(const float*)d_in[2];
    const float* b_ih=(const float*)d_in[3];
    const float* b_hh=(const float*)d_in[4];
    const float* W1=(const float*)d_in[5];
    const float* b1=(const float*)d_in[6];
    const float* W2=(const float*)d_in[7];
    const float* b2=(const float*)d_in[8];
    const float* W3=(const float*)d_in[9];
    const float* b3=(const float*)d_in[10];
    const float* W4=(const float*)d_in[11];
    const float* b4=(const float*)d_in[12];
    const float* Wp=(const float*)d_in[13];
    const float* bp=(const float*)d_in[14];
    float* out=(float*)d_out;
    (void)in_sizes;(void)n_in;(void)out_size;

    void *pWm,*pxin,*px1,*px2,*px3,*px4;
    cudaGetSymbolAddress(&pWm,g_Wm);
    cudaGetSymbolAddress(&pxin,g_xin);
    cudaGetSymbolAddress(&px1,g_x1);
    cudaGetSymbolAddress(&px2,g_x2);
    cudaGetSymbolAddress(&px3,g_x3);
    cudaGetSymbolAddress(&px4,g_x4);
    unsigned short* Wm=(unsigned short*)pWm;

    pack_gru<<<768,272>>>(W_ih,W_hh,b_ih,b_hh);
    pack_mlp<<<1024,256>>>(W1, Wm+WO1, 1024, 271, 288, 1);
    pack_mlp<<<1024,256>>>(W2, Wm+WO2, 1024, 1024, 1024, 0);
    pack_mlp<<<512,256>>>(W3, Wm+WO3, 512, 1024, 1024, 0);
    pack_mlp<<<256,256>>>(W4, Wm+WO4, 256, 512, 512, 0);

    cudaFuncSetAttribute(gru_mma_kernel, cudaFuncAttributeMaxDynamicSharedMemorySize, GRU_SMEM);
    gru_mma_kernel<<<128,256,GRU_SMEM>>>(state);

    cudaFuncSetAttribute(gemm_mma, cudaFuncAttributeMaxDynamicSharedMemorySize, MLP_SMEM);
    gemm_mma<<<dim3(16,128),256,MLP_SMEM>>>((const uint32_t*)pxin, Wm+WO1, b1, (uint32_t*)px1, 288, 1024);
    gemm_mma<<<dim3(16,128),256,MLP_SMEM>>>((const uint32_t*)px1,  Wm+WO2, b2, (uint32_t*)px2, 1024, 1024);
    gemm_mma<<<dim3(8,128),256,MLP_SMEM>>>((const uint32_t*)px2,  Wm+WO3, b3, (uint32_t*)px3, 1024, 512);
    gemm_mma<<<dim3(4,128),256,MLP_SMEM>>>((const uint32_t*)px3,  Wm+WO4, b4, (uint32_t*)px4, 512, 256);
    final_kernel<<<B_TOT/8,256>>>((const uint32_t*)px4, Wp, bp, out);
}

// round 11
// speedup vs baseline: 2.1590x; 1.0265x over previous
#include <cuda_runtime.h>
#include <cuda_bf16.h>
#include <stdint.h>

#define B_TOT 16384
#define V_STEPS 20

// ---- activation buffers: packed bf16 pair (hi<<16 | lo) per element ----
__device__ uint32_t g_xin[B_TOT*288];
__device__ uint32_t g_x1[B_TOT*1024];
__device__ uint32_t g_x2[B_TOT*1024];
__device__ uint32_t g_x3[B_TOT*512];
__device__ uint32_t g_x4[B_TOT*256];
// MLP weights bf16 planes [hl][N][Kp] per layer, concatenated
#define WO1 0
#define WO2 589824
#define WO3 (WO2+2097152)
#define WO4 (WO3+1048576)
__device__ __align__(16) unsigned short g_Wm[WO4+262144];
// GRU packed weights bf16 [hl][768][272] (+pad for tail prefetch)
__device__ __align__(16) unsigned short g_Wg[2*768*272 + 64];
__device__ __align__(16) unsigned short g_Wxn[2*256*16];
__device__ uint32_t g_hstage[128*128*256];

// GRU smem offsets
#define OFF_A_HI 0
#define OFF_A_LO 71680
#define OFF_BXN  143360
#define OFF_BS   167936
#define GRU_SMEM 198656
#define MLP_SMEM 81920

__device__ __forceinline__ float sigmoidf_(float x){ return __fdividef(1.f,1.f+__expf(-x)); }
__device__ __forceinline__ float tanh_(float x){ return __fdividef(2.f,1.f+__expf(-2.f*x))-1.f; }
__device__ __forceinline__ uint32_t smem_u32(const void* p){
    uint32_t a; asm("{ .reg .u64 t; cvta.to.shared.u64 t, %1; cvt.u32.u64 %0, t; }":"=r"(a):"l"(p)); return a;
}
__device__ __forceinline__ void ldsm4(uint32_t a, uint32_t* r){
    asm volatile("ldmatrix.sync.aligned.m8n8.x4.shared.b16 {%0,%1,%2,%3}, [%4];"
        : "=r"(r[0]),"=r"(r[1]),"=r"(r[2]),"=r"(r[3]) : "r"(a));
}
__device__ __forceinline__ void ldsm2(uint32_t a, uint32_t* r){
    asm volatile("ldmatrix.sync.aligned.m8n8.x2.shared.b16 {%0,%1}, [%2];"
        : "=r"(r[0]),"=r"(r[1]) : "r"(a));
}
__device__ __forceinline__ void mma16816(float* d, const uint32_t* a, const uint32_t* b){
    asm volatile("mma.sync.aligned.m16n8k16.row.col.f32.bf16.bf16.f32 "
        "{%0,%1,%2,%3}, {%4,%5,%6,%7}, {%8,%9}, {%0,%1,%2,%3};"
        : "+f"(d[0]),"+f"(d[1]),"+f"(d[2]),"+f"(d[3])
        : "r"(a[0]),"r"(a[1]),"r"(a[2]),"r"(a[3]),"r"(b[0]),"r"(b[1]));
}
__device__ __forceinline__ void bfsplit(float v, unsigned short& h, unsigned short& l){
    __nv_bfloat16 hh=__float2bfloat16(v);
    h=__bfloat16_as_ushort(hh);
    l=__bfloat16_as_ushort(__float2bfloat16(v-__bfloat162float(hh)));
}
__device__ __forceinline__ uint32_t bfpack(float v){
    unsigned short h,l; bfsplit(v,h,l); return ((uint32_t)h<<16)|l;
}
__device__ __forceinline__ float bfunpk(uint32_t p){
    unsigned short h=(unsigned short)(p>>16), l=(unsigned short)(p&0xffffu);
    return __bfloat162float(*(__nv_bfloat16*)&h)+__bfloat162float(*(__nv_bfloat16*)&l);
}

// ---------------- pack kernels ----------------
__global__ void pack_gru(const float* __restrict__ W_ih, const float* __restrict__ W_hh,
                         const float* __restrict__ b_ih, const float* __restrict__ b_hh){
    int g=blockIdx.x, k=threadIdx.x;
    int gate=g>>8;
    float v;
    if(k<15)       v = (gate==2)? 0.f : W_ih[g*15+k];
    else if(k==15) v = (gate==2)? b_hh[g] : (b_ih[g]+b_hh[g]);
    else           v = W_hh[g*256+(k-16)];
    unsigned short h,l; bfsplit(v,h,l);
    g_Wg[g*272+k]=h; g_Wg[208896+g*272+k]=l;
    if(g>=512 && k<16){
        float w = (k<15)? W_ih[g*15+k] : b_ih[g];
        unsigned short h2,l2; bfsplit(w,h2,l2);
        g_Wxn[(g-512)*16+k]=h2; g_Wxn[4096+(g-512)*16+k]=l2;
    }
}
__global__ void pack_mlp(const float* __restrict__ W, unsigned short* __restrict__ dst,
                         int N, int K, int Kp, int l1mode){
    int n=blockIdx.x;
    for(int k=threadIdx.x;k<Kp;k+=256){
        float v=0.f;
        if(l1mode){ if(k<15) v=W[n*271+k]; else if(k>=16&&k<272) v=W[n*271+k-1]; }
        else if(k<K) v=W[(size_t)n*K+k];
        unsigned short h,l; bfsplit(v,h,l);
        dst[(size_t)n*Kp+k]=h;
        dst[(size_t)N*Kp+(size_t)n*Kp+k]=l;
    }
}

// ---------------- GRU: mma.sync bf16-split, persistent 20 steps (unchanged) ----------------
__global__ __launch_bounds__(256,1) void gru_mma_kernel(const float* __restrict__ state){
    extern __shared__ __align__(16) unsigned char sm[];
    const uint32_t sb=smem_u32(sm);
    const int tid=threadIdx.x, wid=tid>>5, l=tid&31, ll=l&15;
    const int wm=wid&1, wn=wid>>1;
    const int cta=blockIdx.x, bbase=cta*128;

    for(int i=tid;i<143360/16;i+=256) ((uint4*)sm)[i]=make_uint4(0,0,0,0);
    for(int i=tid;i<1024;i+=256){
        int u=i&1, n=(i>>1)&255, hl=i>>9;
        uint4 v=*(const uint4*)(g_Wxn + hl*4096 + n*16 + u*8);
        *(uint4*)(sm+OFF_BXN + hl*12288 + n*48 + u*16)=v;
    }
    __syncthreads();

    const uint32_t aoff  = (uint32_t)(ll*560 + (l>>4)*16);
    const uint32_t boffn = (uint32_t)((l&7)*80 + (ll>>3)*16) + wn*8*80;
    const uint32_t bxoff = (uint32_t)((l&7)*48 + (ll>>3)*16) + wn*8*48;

    for(int t=0;t<V_STEPS;t++){
        {
            int row=tid>>1, k0=(tid&1)*8;
            union{uint4 q; unsigned short s[8];} hi,lo;
            #pragma unroll
            for(int j=0;j<8;j++){
                int k=k0+j;
                float v=(k<15)? state[(size_t)(bbase+row)*300+t*15+k] : (k==15?1.f:0.f);
                bfsplit(v,hi.s[j],lo.s[j]);
            }
            *(uint4*)(sm+OFF_A_HI+row*560+k0*2)=hi.q;
            *(uint4*)(sm+OFF_A_LO+row*560+k0*2)=lo.q;
        }
        __syncthreads();

        for(int hb=0;hb<8;hb++){
            float aR[4][4],aZ[4][4],aH[4][4],aX[4][4];
            #pragma unroll
            for(int m2=0;m2<4;m2++)
                #pragma unroll
                for(int e=0;e<4;e++){ aR[m2][e]=0.f;aZ[m2][e]=0.f;aH[m2][e]=0.f;aX[m2][e]=0.f; }

            uint32_t bxh[2],bxl[2];
            { uint32_t a0=sb+OFF_BXN + hb*32*48 + bxoff;
              ldsm2(a0,bxh); ldsm2(a0+12288,bxl); }

            uint4 ldv[3];
            #pragma unroll
            for(int j=0;j<3;j++){
                int i=tid+j*256, u=i&3, n=(i>>2)&31, gh=i>>7;
                ldv[j]=*(const uint4*)(g_Wg + (gh&1)*208896 + ((gh>>1)*256+hb*32+n)*272 + u*8);
            }
            #pragma unroll
            for(int j=0;j<3;j++){
                int i=tid+j*256, u=i&3, n=(i>>2)&31, gh=i>>7;
                *(uint4*)(sm+OFF_BS + (gh*32+n)*80 + u*16)=ldv[j];
            }
            __syncthreads();

            for(int kc=0;kc<9;kc++){
                int buf=kc&1;
                if(kc<8){
                    #pragma unroll
                    for(int j=0;j<3;j++){
                        int i=tid+j*256, u=i&3, n=(i>>2)&31, gh=i>>7;
                        ldv[j]=*(const uint4*)(g_Wg + (gh&1)*208896 +
                               ((gh>>1)*256+hb*32+n)*272 + (kc+1)*32 + u*8);
                    }
                }
                const int ns=(kc==8)?1:2;
                for(int s=0;s<ns;s++){
                    uint32_t bh[3][2], bl[3][2];
                    #pragma unroll
                    for(int g=0;g<3;g++){
                        uint32_t base=sb+OFF_BS + buf*15360 + g*2*2560 + boffn + s*32;
                        ldsm2(base, bh[g]); ldsm2(base+2560, bl[g]);
                    }
                    #pragma unroll
                    for(int mt=0;mt<4;mt++){
                        uint32_t ah[4],al[4];
                        uint32_t abase=sb + (wm*64+mt*16)*560 + kc*64 + s*32 + aoff;
                        ldsm4(abase+OFF_A_HI, ah);
                        ldsm4(abase+OFF_A_LO, al);
                        mma16816(aR[mt],ah,bh[0]); mma16816(aR[mt],al,bh[0]); mma16816(aR[mt],ah,bl[0]);
                        mma16816(aZ[mt],ah,bh[1]); mma16816(aZ[mt],al,bh[1]); mma16816(aZ[mt],ah,bl[1]);
                        mma16816(aH[mt],ah,bh[2]); mma16816(aH[mt],al,bh[2]); mma16816(aH[mt],ah,bl[2]);
                        if(kc==0 && s==0){
                            mma16816(aX[mt],ah,bxh); mma16816(aX[mt],al,bxh); mma16816(aX[mt],ah,bxl);
                        }
                    }
                }
                if(kc<8){
                    #pragma unroll
                    for(int j=0;j<3;j++){
                        int i=tid+j*256, u=i&3, n=(i>>2)&31, gh=i>>7;
                        *(uint4*)(sm+OFF_BS + (buf^1)*15360 + (gh*32+n)*80 + u*16)=ldv[j];
                    }
                    __syncthreads();
                }
            }
            #pragma unroll
            for(int mt=0;mt<4;mt++){
                #pragma unroll
                for(int e=0;e<4;e++){
                    int row=wm*64+mt*16+(l>>2)+(e>>1)*8;
                    int hcol=hb*32+wn*8+2*(l&3)+(e&1);
                    float hp=__bfloat162float(*(__nv_bfloat16*)(sm+OFF_A_HI+row*560+(16+hcol)*2))
                            +__bfloat162float(*(__nv_bfloat16*)(sm+OFF_A_LO+row*560+(16+hcol)*2));
                    float r=sigmoidf_(aR[mt][e]), z=sigmoidf_(aZ[mt][e]);
                    float n=tanh_(fmaf(r,aH[mt][e],aX[mt][e]));
                    float hv=(1.f-z)*n+z*hp;
                    unsigned short hs,ls; bfsplit(hv,hs,ls);
                    g_hstage[(size_t)cta*32768 + row*256 + hcol]=((uint32_t)hs<<16)|ls;
                }
            }
            __syncthreads();
        } // hb

        {
            int row=tid>>1, cb=(tid&1)*128;
            const uint4* src=(const uint4*)(g_hstage + (size_t)cta*32768 + row*256 + cb);
            #pragma unroll
            for(int g8=0;g8<16;g8++){
                uint4 w0=src[g8*2], w1=src[g8*2+1];
                uint32_t ws[8]={w0.x,w0.y,w0.z,w0.w,w1.x,w1.y,w1.z,w1.w};
                union{uint4 q;unsigned short s[8];} hi,lo;
                #pragma unroll
                for(int j=0;j<8;j++){ hi.s[j]=(unsigned short)(ws[j]>>16); lo.s[j]=(unsigned short)(ws[j]&0xFFFFu); }
                *(uint4*)(sm+OFF_A_HI+row*560+(16+cb+g8*8)*2)=hi.q;
                *(uint4*)(sm+OFF_A_LO+row*560+(16+cb+g8*8)*2)=lo.q;
            }
        }
        __syncthreads();
    } // t

    for(int i=tid;i<128*288;i+=256){
        int r=i/288, c=i-r*288;
        uint32_t pk;
        if(c<15) pk=bfpack(state[(size_t)(bbase+r)*300+c]);
        else if(c==15 || c>=272) pk=0u;
        else pk=((uint32_t)(*(unsigned short*)(sm+OFF_A_HI+r*560+c*2))<<16)
               | (uint32_t)(*(unsigned short*)(sm+OFF_A_LO+r*560+c*2));
        g_xin[(size_t)(bbase+r)*288+c]=pk;
    }
}

// ---------------- MLP GEMM: mma.sync bf16-split, 128x128 tile ----------------
// C[M,N] = relu(A@W^T + b); A packed u32 [M][Kp]; W planes [hl][N][Kp]; C packed u32.
// 8 warps (2m x 4n); warp tile 64x32; k-chunks of 32, double buffered.
// smem: A[buf][hl][128][80B] = 40960; B[buf][hl][128][80B] at 40960.
__global__ __launch_bounds__(256) void gemm_mma(const uint32_t* __restrict__ A,
        const unsigned short* __restrict__ W, const float* __restrict__ bias,
        uint32_t* __restrict__ C, int Kp, int N){
    extern __shared__ __align__(16) unsigned char sm[];
    const uint32_t sb=smem_u32(sm);
    const int tid=threadIdx.x, wid=tid>>5, l=tid&31;
    const int wm=wid&1, wn=wid>>1;
    const int nb=blockIdx.x*128, mb=blockIdx.y*128;
    const int nch=Kp>>5;
    const size_t wplane=(size_t)N*Kp;

    float acc[4][4][4];
    #pragma unroll
    for(int mt=0;mt<4;mt++)
        #pragma unroll
        for(int ng=0;ng<4;ng++)
            #pragma unroll
            for(int e=0;e<4;e++) acc[mt][ng][e]=0.f;

    const int arow=tid>>3, au=tid&7;        // A: 4 rows/thread (stride 32), 16B per row-seg
    const int brow=tid>>1, bu=tid&1;        // B: 1 row/thread, 32B per plane (2 uint4)
    uint4 av[4], bv[2][2];

    #define LOAD_AB(kc) { \
        _Pragma("unroll") \
        for(int j=0;j<4;j++) \
            av[j]=*(const uint4*)(A + (size_t)(mb+arow+j*32)*Kp + (kc)*32 + au*4); \
        _Pragma("unroll") \
        for(int i2=0;i2<2;i2++){ \
            bv[0][i2]=*(const uint4*)(W + (size_t)(nb+brow)*Kp + (kc)*32 + bu*16 + i2*8); \
            bv[1][i2]=*(const uint4*)(W + wplane + (size_t)(nb+brow)*Kp + (kc)*32 + bu*16 + i2*8); } }
    #define STORE_AB(buf) { \
        _Pragma("unroll") \
        for(int j=0;j<4;j++){ \
            uint4 v=av[j]; int ro=(arow+j*32)*80+au*8; \
            *(uint2*)(sm + (buf)*20480 + ro) = \
                make_uint2((v.x>>16)|(v.y&0xffff0000u),(v.z>>16)|(v.w&0xffff0000u)); \
            *(uint2*)(sm + 10240 + (buf)*20480 + ro) = \
                make_uint2((v.x&0xffffu)|(v.y<<16),(v.z&0xffffu)|(v.w<<16)); } \
        _Pragma("unroll") \
        for(int i2=0;i2<2;i2++){ \
            *(uint4*)(sm + 40960 + (buf)*20480 + brow*80 + bu*32 + i2*16)=bv[0][i2]; \
            *(uint4*)(sm + 40960 + (buf)*20480 + 10240 + brow*80 + bu*32 + i2*16)=bv[1][i2]; } }

    LOAD_AB(0); STORE_AB(0);
    __syncthreads();

    const uint32_t aoff=(uint32_t)((l&15)*80 + (l>>4)*16);
    const uint32_t boff=(uint32_t)((wn*32+(l&7))*80 + ((l>>3)&1)*16);

    for(int kc=0;kc<nch;kc++){
        int buf=kc&1;
        if(kc+1<nch) LOAD_AB(kc+1);
        #pragma unroll
        for(int s=0;s<2;s++){
            uint32_t bh[4][2], bl[4][2];
            #pragma unroll
            for(int ng=0;ng<4;ng++){
                uint32_t base=sb + 40960 + buf*20480 + boff + ng*8*80 + s*32;
                ldsm2(base, bh[ng]); ldsm2(base+10240, bl[ng]);
            }
            #pragma unroll
            for(int mt=0;mt<4;mt++){
                uint32_t ah[4],al[4];
                uint32_t abase=sb + buf*20480 + (wm*64+mt*16)*80 + s*32 + aoff;
                ldsm4(abase, ah); ldsm4(abase+10240, al);
                #pragma unroll
                for(int ng=0;ng<4;ng++){
                    mma16816(acc[mt][ng],ah,bh[ng]);
                    mma16816(acc[mt][ng],al,bh[ng]);
                    mma16816(acc[mt][ng],ah,bl[ng]);
                }
            }
        }
        if(kc+1<nch){ STORE_AB(buf^1); __syncthreads(); }
    }

    #pragma unroll
    for(int mt=0;mt<4;mt++)
        #pragma unroll
        for(int ng=0;ng<4;ng++)
            #pragma unroll
            for(int e=0;e<4;e++){
                int row=mb + wm*64+mt*16+(l>>2)+(e>>1)*8;
                int col=nb + wn*32+ng*8+2*(l&3)+(e&1);
                float v=fmaxf(acc[mt][ng][e]+__ldg(bias+col),0.f);
                C[(size_t)row*N+col]=bfpack(v);
            }
    #undef LOAD_AB
    #undef STORE_AB
}

// ---------------- final layer ----------------
__global__ __launch_bounds__(256)
void final_kernel(const uint32_t* __restrict__ x4, const float* __restrict__ Wp,
                  const float* __restrict__ bp, float* __restrict__ out){
    int warp=(blockIdx.x*256+threadIdx.x)>>5, lane=threadIdx.x&31;
    if(warp>=B_TOT) return;
    const uint32_t* row=x4+(size_t)warp*256;
    float s=0.f;
    #pragma unroll
    for(int c=lane;c<256;c+=32) s+=bfunpk(row[c])*Wp[c];
    #pragma unroll
    for(int o=16;o;o>>=1) s+=__shfl_xor_sync(0xffffffffu,s,o);
    if(lane==0) out[warp]=tanh_(s+bp[0]);
}

// ---------------- host launcher ----------------
extern "C" void kernel_launch(void* const* d_in, const int* in_sizes, int n_in,
                              void* d_out, int out_size){
    const float* state=(const float*)d_in[0];
    const float* W_ih=(const float*)d_in[1];
    const float* W_hh=(const float*)d_in[2];
    const float* b_ih=(const float*)d_in[3];
    const float* b_hh=(const float*)d_in[4];
    const float* W1=(const float*)d_in[5];
    const float* b1=(const float*)d_in[6];
    const float* W2=(const float*)d_in[7];
    const float* b2=(const float*)d_in[8];
    const float* W3=(const float*)d_in[9];
    const float* b3=(const float*)d_in[10];
    const float* W4=(const float*)d_in[11];
    const float* b4=(const float*)d_in[12];
    const float* Wp=(const float*)d_in[13];
    const float* bp=(const float*)d_in[14];
    float* out=(float*)d_out;
    (void)in_sizes;(void)n_in;(void)out_size;

    void *pWm,*pxin,*px1,*px2,*px3,*px4;
    cudaGetSymbolAddress(&pWm,g_Wm);
    cudaGetSymbolAddress(&pxin,g_xin);
    cudaGetSymbolAddress(&px1,g_x1);
    cudaGetSymbolAddress(&px2,g_x2);
    cudaGetSymbolAddress(&px3,g_x3);
    cudaGetSymbolAddress(&px4,g_x4);
    unsigned short* Wm=(unsigned short*)pWm;

    pack_gru<<<768,272>>>(W_ih,W_hh,b_ih,b_hh);
    pack_mlp<<<1024,256>>>(W1, Wm+WO1, 1024, 271, 288, 1);
    pack_mlp<<<1024,256>>>(W2, Wm+WO2, 1024, 1024, 1024, 0);
    pack_mlp<<<512,256>>>(W3, Wm+WO3, 512, 1024, 1024, 0);
    pack_mlp<<<256,256>>>(W4, Wm+WO4, 256, 512, 512, 0);

    cudaFuncSetAttribute(gru_mma_kernel, cudaFuncAttributeMaxDynamicSharedMemorySize, GRU_SMEM);
    gru_mma_kernel<<<128,256,GRU_SMEM>>>(state);

    cudaFuncSetAttribute(gemm_mma, cudaFuncAttributeMaxDynamicSharedMemorySize, MLP_SMEM);
    gemm_mma<<<dim3(8,128),256,MLP_SMEM>>>((const uint32_t*)pxin, Wm+WO1, b1, (uint32_t*)px1, 288, 1024);
    gemm_mma<<<dim3(8,128),256,MLP_SMEM>>>((const uint32_t*)px1,  Wm+WO2, b2, (uint32_t*)px2, 1024, 1024);
    gemm_mma<<<dim3(4,128),256,MLP_SMEM>>>((const uint32_t*)px2,  Wm+WO3, b3, (uint32_t*)px3, 1024, 512);
    gemm_mma<<<dim3(2,128),256,MLP_SMEM>>>((const uint32_t*)px3,  Wm+WO4, b4, (uint32_t*)px4, 512, 256);
    final_kernel<<<B_TOT/8,256>>>((const uint32_t*)px4, Wp, bp, out);
}